// round 12
// baseline (speedup 1.0000x reference)
#include <cuda_runtime.h>
#include <cuda_fp16.h>
#include <cstdint>

#define B_  8
#define S_  2048
#define D_  768
#define M1  (B_ * S_)

// ---------------- fp16 GEMM config ----------------
#define BM 128
#define BN 128
#define HBK 32                 // halves per k-tile
#define HSTRIDE 40             // halves per row in smem (pad 32->40)
#define HST 4
#define H_A_BYTES (BM * HSTRIDE * 2)   // 10240
#define H_STAGE_BYTES (2 * H_A_BYTES)  // A + B = 20480

// ---------------- scratch ----------------
__device__ __half g_Xh [3][(size_t)M1 * D_];       // fp16 inputs q,k,v
__device__ __half g_Wth[3][(size_t)D_ * D_];       // fp16 W transposed [n][k]
__device__ __half g_Qh [(size_t)M1 * D_];
__device__ __half g_Kh [(size_t)M1 * D_];
__device__ __half g_Vh [(size_t)M1 * D_];
__device__ __half g_Vth[(size_t)B_ * D_ * S_];     // V transposed [b][d][s]
__device__ float  g_S  [(size_t)B_ * S_ * S_];     // raw scores fp32
__device__ __half g_P  [(size_t)B_ * S_ * S_];     // probs fp16

// ---------------- JAX threefry2x32 (bit-exact, verified R1) ----------------
__device__ __forceinline__ uint32_t rotl32(uint32_t x, uint32_t d) {
    return (x << d) | (x >> (32u - d));
}
__device__ __forceinline__ float tf_uniform(uint32_t idx) {
    const uint32_t K0 = 0u, K1 = 42u, K2 = 0x1BD11BDAu ^ 42u;
    uint32_t x0 = 0u + K0, x1 = idx + K1;
#define TF_R4(a,b,c,d) \
    x0 += x1; x1 = rotl32(x1,(a)); x1 ^= x0; \
    x0 += x1; x1 = rotl32(x1,(b)); x1 ^= x0; \
    x0 += x1; x1 = rotl32(x1,(c)); x1 ^= x0; \
    x0 += x1; x1 = rotl32(x1,(d)); x1 ^= x0;
    TF_R4(13,15,26, 6)  x0 += K1; x1 += K2 + 1u;
    TF_R4(17,29,16,24)  x0 += K2; x1 += K0 + 2u;
    TF_R4(13,15,26, 6)  x0 += K0; x1 += K1 + 3u;
    TF_R4(17,29,16,24)  x0 += K1; x1 += K2 + 4u;
    TF_R4(13,15,26, 6)  x0 += K2; x1 += K0 + 5u;
#undef TF_R4
    uint32_t bits = x0 ^ x1;
    return __uint_as_float((bits >> 9) | 0x3f800000u) - 1.0f;
}

// ---------------- helpers ----------------
__device__ __forceinline__ void mma_f16(float (&c)[4], const uint32_t (&a)[4],
                                        const uint32_t (&b)[2]) {
    asm volatile(
        "mma.sync.aligned.m16n8k16.row.col.f32.f16.f16.f32 "
        "{%0,%1,%2,%3}, {%4,%5,%6,%7}, {%8,%9}, {%0,%1,%2,%3};"
        : "+f"(c[0]), "+f"(c[1]), "+f"(c[2]), "+f"(c[3])
        : "r"(a[0]), "r"(a[1]), "r"(a[2]), "r"(a[3]), "r"(b[0]), "r"(b[1]));
}
__device__ __forceinline__ void ldsm_x4(uint32_t& r0, uint32_t& r1,
                                        uint32_t& r2, uint32_t& r3,
                                        uint32_t addr) {
    asm volatile(
        "ldmatrix.sync.aligned.m8n8.x4.shared.b16 {%0,%1,%2,%3}, [%4];"
        : "=r"(r0), "=r"(r1), "=r"(r2), "=r"(r3) : "r"(addr));
}
__device__ __forceinline__ void cpa16(uint32_t sa, const void* g) {
    asm volatile("cp.async.cg.shared.global [%0], [%1], 16;" :: "r"(sa), "l"(g));
}
__device__ __forceinline__ void cpa_commit() {
    asm volatile("cp.async.commit_group;");
}
template <int N>
__device__ __forceinline__ void cpa_wait() {
    asm volatile("cp.async.wait_group %0;" :: "n"(N));
}

// ============ fp16 pipelined GEMM: C = A @ B^T, A [M][K], B [N][K] halves ===
// LDSM fragment loads: 4x A (one per m16 tile), 2x B (each covers two n8).
__device__ __forceinline__ void gemm_h(const __half* __restrict__ A,
                                       const __half* __restrict__ Bm,
                                       int K, int row0, int col0,
                                       float (&acc)[4][4][4]) {
    extern __shared__ float smf[];
    __half* sm = reinterpret_cast<__half*>(smf);
    const uint32_t sbase = (uint32_t)__cvta_generic_to_shared(sm);
    const int tid  = threadIdx.x;
    const int lane = tid & 31, warp = tid >> 5;
    const int wm = (warp & 1) * 64;
    const int wn = (warp >> 1) * 32;

#pragma unroll
    for (int mi = 0; mi < 4; ++mi)
#pragma unroll
        for (int ni = 0; ni < 4; ++ni)
#pragma unroll
            for (int q = 0; q < 4; ++q) acc[mi][ni][q] = 0.0f;

    // ldmatrix per-lane offsets (halves, relative to stage start)
    const int lane15 = lane & 15;
    const int colsel = (lane >> 4) << 3;       // 0 or 8 (k side)
    int offA[4], offB[2];
#pragma unroll
    for (int mi = 0; mi < 4; ++mi)
        offA[mi] = (wm + mi * 16 + lane15) * HSTRIDE + colsel;
#pragma unroll
    for (int p = 0; p < 2; ++p)
        offB[p] = BM * HSTRIDE + (wn + p * 16 + lane15) * HSTRIDE + colsel;

    auto load_stage = [&](int s, int it) {
        const int k0 = it * HBK;
        const uint32_t st = sbase + (uint32_t)s * H_STAGE_BYTES;
#pragma unroll
        for (int p = 0; p < 2; ++p) {           // A: 128 rows x 4 chunks(8 halves)
            const int c  = tid + (p << 8);
            const int r  = c >> 2;
            const int ch = c & 3;
            cpa16(st + (uint32_t)(r * HSTRIDE + ch * 8) * 2u,
                  A + (size_t)(row0 + r) * K + k0 + ch * 8);
        }
#pragma unroll
        for (int p = 0; p < 2; ++p) {           // B: 128 rows x 4 chunks
            const int c  = tid + (p << 8);
            const int r  = c >> 2;
            const int ch = c & 3;
            cpa16(st + H_A_BYTES + (uint32_t)(r * HSTRIDE + ch * 8) * 2u,
                  Bm + (size_t)(col0 + r) * K + k0 + ch * 8);
        }
    };

    const int nk = K / HBK;
#pragma unroll
    for (int p = 0; p < HST - 1; ++p) { load_stage(p, p); cpa_commit(); }

    for (int i = 0; i < nk; ++i) {
        cpa_wait<HST - 2>();
        __syncthreads();
        const int ld = i + HST - 1;
        if (ld < nk) load_stage(ld & (HST - 1), ld);
        cpa_commit();

        const uint32_t su = sbase + (uint32_t)(i & (HST - 1)) * H_STAGE_BYTES;
#pragma unroll
        for (int ks = 0; ks < HBK / 16; ++ks) {
            const int k = ks << 4;
            uint32_t a[4][4];
#pragma unroll
            for (int mi = 0; mi < 4; ++mi)
                ldsm_x4(a[mi][0], a[mi][1], a[mi][2], a[mi][3],
                        su + (uint32_t)(offA[mi] + k) * 2u);
            uint32_t b[4][2];
#pragma unroll
            for (int p = 0; p < 2; ++p)
                ldsm_x4(b[2 * p][0], b[2 * p + 1][0],
                        b[2 * p][1], b[2 * p + 1][1],
                        su + (uint32_t)(offB[p] + k) * 2u);
#pragma unroll
            for (int mi = 0; mi < 4; ++mi)
#pragma unroll
                for (int ni = 0; ni < 4; ++ni)
                    mma_f16(acc[mi][ni], a[mi], b[ni]);
        }
    }
    cpa_wait<0>();
}

// ---------------- kernel 0a: convert q/k/v fp32 -> fp16 ----------------
struct XArgs { const float* X[3]; };

__global__ __launch_bounds__(256)
void convert_x_kernel(XArgs xa) {
    const int z = blockIdx.z;
    const float* X = xa.X[z];
    __half* O = g_Xh[z];
    const size_t i = ((size_t)blockIdx.x * 256 + threadIdx.x) * 4;
    float4 v = *reinterpret_cast<const float4*>(X + i);
    __half2 h0 = __floats2half2_rn(v.x, v.y);
    __half2 h1 = __floats2half2_rn(v.z, v.w);
    *reinterpret_cast<__half2*>(O + i)     = h0;
    *reinterpret_cast<__half2*>(O + i + 2) = h1;
}

// ---------------- kernel 0b: W [K][N] -> Wt fp16 [N][K] ----------------
struct WArgs { const float* W[3]; };

__global__ __launch_bounds__(256)
void convert_w_kernel(WArgs wa) {
    __shared__ float tile[32][33];
    const int z = blockIdx.z;
    const float* W = wa.W[z];
    __half* Wt = g_Wth[z];
    const int bx = blockIdx.x * 32, by = blockIdx.y * 32;
    const int tx = threadIdx.x & 31, ty = (threadIdx.x >> 5) * 4;
#pragma unroll
    for (int i = 0; i < 4; ++i)
        tile[ty + i][tx] = W[(size_t)(by + ty + i) * D_ + bx + tx];
    __syncthreads();
#pragma unroll
    for (int i = 0; i < 4; ++i)
        Wt[(size_t)(bx + ty + i) * D_ + by + tx] = __float2half_rn(tile[tx][ty + i]);
}

// ---------------- kernel 1: fused Q/K/V projections (fp16 GEMM) ------------
struct ProjArgs { const float* b[3]; };

__global__ __launch_bounds__(256, 2)
void proj_kernel(ProjArgs pa) {
    const int z = blockIdx.z;
    const int row0 = blockIdx.y * BM, col0 = blockIdx.x * BN;
    float acc[4][4][4];
    gemm_h(g_Xh[z], g_Wth[z], D_, row0, col0, acc);

    const float* bias = pa.b[z];
    __half* C = (z == 0) ? g_Qh : (z == 1) ? g_Kh : g_Vh;
    const int tid = threadIdx.x, lane = tid & 31, warp = tid >> 5;
    const int rw0 = row0 + (warp & 1) * 64 + (lane >> 2);
    const int cw0 = col0 + (warp >> 1) * 32 + (lane & 3) * 2;
#pragma unroll
    for (int mi = 0; mi < 4; ++mi) {
#pragma unroll
        for (int ni = 0; ni < 4; ++ni) {
            const int c = cw0 + (ni << 3);
            const float bx = __ldg(bias + c), by = __ldg(bias + c + 1);
            const int r1 = rw0 + (mi << 4);
            __half2 h0 = __floats2half2_rn(acc[mi][ni][0] + bx, acc[mi][ni][1] + by);
            __half2 h1 = __floats2half2_rn(acc[mi][ni][2] + bx, acc[mi][ni][3] + by);
            *reinterpret_cast<__half2*>(C + (size_t)r1 * D_ + c)       = h0;
            *reinterpret_cast<__half2*>(C + (size_t)(r1 + 8) * D_ + c) = h1;
        }
    }
}

// ---------------- kernel 1b: transpose V (fp16) [b][s][d] -> [b][d][s] -----
__global__ __launch_bounds__(256)
void transpose_v_kernel() {
    __shared__ __half tile[64][65];
    const int b = blockIdx.z;
    const int s0 = blockIdx.x * 64, d0 = blockIdx.y * 64;
    const __half* in = g_Vh + (size_t)b * S_ * D_;
    __half* out = g_Vth + (size_t)b * D_ * S_;
    const int tid = threadIdx.x;
#pragma unroll
    for (int i = 0; i < 16; ++i) {
        const int idx = tid + (i << 8);
        const int r = idx >> 6, c = idx & 63;
        tile[r][c] = in[(size_t)(s0 + r) * D_ + d0 + c];
    }
    __syncthreads();
#pragma unroll
    for (int i = 0; i < 16; ++i) {
        const int idx = tid + (i << 8);
        const int r = idx >> 6, c = idx & 63;
        out[(size_t)(d0 + r) * S_ + s0 + c] = tile[c][r];
    }
}

// ------- kernel 2: scores = (Q K^T)/sqrt(D) + pre-softmax dropout (fp32 out)
__global__ __launch_bounds__(256, 2)
void scores_kernel() {
    const int bz = blockIdx.z;
    const int row0 = blockIdx.y * BM, col0 = blockIdx.x * BN;
    float acc[4][4][4];
    gemm_h(g_Qh + (size_t)bz * S_ * D_, g_Kh + (size_t)bz * S_ * D_,
           D_, row0, col0, acc);

    float* C = g_S + (size_t)bz * S_ * S_;
    const int tid = threadIdx.x, lane = tid & 31, warp = tid >> 5;
    const int rw0 = row0 + (warp & 1) * 64 + (lane >> 2);
    const int cw0 = col0 + (warp >> 1) * 32 + (lane & 3) * 2;
    const float sc = 0.03608439182435161f;  // 1/sqrt(768)
#pragma unroll
    for (int mi = 0; mi < 4; ++mi) {
#pragma unroll
        for (int rr = 0; rr < 2; ++rr) {
            const int r = rw0 + (mi << 4) + (rr << 3);
            const uint32_t ib = ((uint32_t)bz * S_ + (uint32_t)r) * (uint32_t)S_;
#pragma unroll
            for (int ni = 0; ni < 4; ++ni) {
                const int c = cw0 + (ni << 3);
                const float v0 = acc[mi][ni][rr * 2 + 0] * sc;
                const float v1 = acc[mi][ni][rr * 2 + 1] * sc;
                const float u0 = tf_uniform(ib + (uint32_t)c);
                const float u1 = tf_uniform(ib + (uint32_t)c + 1u);
                float2 o;
                o.x = (u0 < 0.8f) ? v0 * 1.25f : 0.0f;
                o.y = (u1 < 0.8f) ? v1 * 1.25f : 0.0f;
                *reinterpret_cast<float2*>(C + (size_t)r * S_ + c) = o;
            }
        }
    }
}

// ------ kernel 3: softmax over k, post-softmax mask, write fp16 probs ------
__global__ __launch_bounds__(256)
void softmax_mask_kernel(const int* __restrict__ mask) {
    const int row = blockIdx.x;
    const float* srow = g_S + (size_t)row * S_;
    __half* prow = g_P + (size_t)row * S_;
    const int* mrow = mask + (size_t)row * S_;
    const int t = threadIdx.x;
    __shared__ float red[8];

    float4 v4[2];
    v4[0] = *reinterpret_cast<const float4*>(srow + (t << 2));
    v4[1] = *reinterpret_cast<const float4*>(srow + 1024 + (t << 2));
    float* v = reinterpret_cast<float*>(v4);

    float mx = v[0];
#pragma unroll
    for (int i = 1; i < 8; ++i) mx = fmaxf(mx, v[i]);
#pragma unroll
    for (int o = 16; o > 0; o >>= 1)
        mx = fmaxf(mx, __shfl_xor_sync(0xffffffffu, mx, o));
    if ((t & 31) == 0) red[t >> 5] = mx;
    __syncthreads();
    if (t < 32) {
        float m2 = (t < 8) ? red[t] : -3.4e38f;
#pragma unroll
        for (int o = 4; o > 0; o >>= 1)
            m2 = fmaxf(m2, __shfl_xor_sync(0xffffffffu, m2, o));
        if (t == 0) red[0] = m2;
    }
    __syncthreads();
    mx = red[0];
    __syncthreads();

    float sum = 0.0f;
#pragma unroll
    for (int i = 0; i < 8; ++i) { v[i] = __expf(v[i] - mx); sum += v[i]; }
#pragma unroll
    for (int o = 16; o > 0; o >>= 1)
        sum += __shfl_xor_sync(0xffffffffu, sum, o);
    if ((t & 31) == 0) red[t >> 5] = sum;
    __syncthreads();
    if (t < 32) {
        float s2 = (t < 8) ? red[t] : 0.0f;
#pragma unroll
        for (int o = 4; o > 0; o >>= 1)
            s2 += __shfl_xor_sync(0xffffffffu, s2, o);
        if (t == 0) red[0] = s2;
    }
    __syncthreads();
    const float inv = 1.0f / red[0];

    int4 m4[2];
    m4[0] = *reinterpret_cast<const int4*>(mrow + (t << 2));
    m4[1] = *reinterpret_cast<const int4*>(mrow + 1024 + (t << 2));
    const int* m = reinterpret_cast<const int*>(m4);
#pragma unroll
    for (int i = 0; i < 8; ++i)
        v[i] = (m[i] == 0) ? 1e-9f : v[i] * inv;
#pragma unroll
    for (int p = 0; p < 2; ++p) {
        __half2 h0 = __floats2half2_rn(v[p * 4 + 0], v[p * 4 + 1]);
        __half2 h1 = __floats2half2_rn(v[p * 4 + 2], v[p * 4 + 3]);
        const int base = p * 1024 + (t << 2);
        *reinterpret_cast<__half2*>(prow + base)     = h0;
        *reinterpret_cast<__half2*>(prow + base + 2) = h1;
    }
}

// -------- kernel 4: out = att @ V  (A = probs fp16, B = Vt fp16 BTRANS) ----
__global__ __launch_bounds__(256, 2)
void out_kernel(float* __restrict__ Og) {
    const int bz = blockIdx.z;
    const int row0 = blockIdx.y * BM, col0 = blockIdx.x * BN;
    float acc[4][4][4];
    gemm_h(g_P + (size_t)bz * S_ * S_, g_Vth + (size_t)bz * D_ * S_,
           S_, row0, col0, acc);

    float* C = Og + (size_t)bz * S_ * D_;
    const int tid = threadIdx.x, lane = tid & 31, warp = tid >> 5;
    const int rw0 = row0 + (warp & 1) * 64 + (lane >> 2);
    const int cw0 = col0 + (warp >> 1) * 32 + (lane & 3) * 2;
#pragma unroll
    for (int mi = 0; mi < 4; ++mi) {
#pragma unroll
        for (int ni = 0; ni < 4; ++ni) {
            const int c = cw0 + (ni << 3);
            const int r1 = rw0 + (mi << 4);
            float2 o0 = make_float2(acc[mi][ni][0], acc[mi][ni][1]);
            float2 o1 = make_float2(acc[mi][ni][2], acc[mi][ni][3]);
            *reinterpret_cast<float2*>(C + (size_t)r1 * D_ + c)       = o0;
            *reinterpret_cast<float2*>(C + (size_t)(r1 + 8) * D_ + c) = o1;
        }
    }
}

// ---------------- launch ----------------
extern "C" void kernel_launch(void* const* d_in, const int* in_sizes, int n_in,
                              void* d_out, int out_size) {
    const int* mask = (const int*)d_in[3];

    XArgs xa;
    xa.X[0] = (const float*)d_in[0];
    xa.X[1] = (const float*)d_in[1];
    xa.X[2] = (const float*)d_in[2];

    WArgs wa;
    wa.W[0] = (const float*)d_in[4];
    wa.W[1] = (const float*)d_in[6];
    wa.W[2] = (const float*)d_in[8];

    ProjArgs pa;
    pa.b[0] = (const float*)d_in[5];
    pa.b[1] = (const float*)d_in[7];
    pa.b[2] = (const float*)d_in[9];

    const int smem_h = H_STAGE_BYTES * HST;          // 81920 B
    cudaFuncSetAttribute(proj_kernel,
        cudaFuncAttributeMaxDynamicSharedMemorySize, smem_h);
    cudaFuncSetAttribute(scores_kernel,
        cudaFuncAttributeMaxDynamicSharedMemorySize, smem_h);
    cudaFuncSetAttribute(out_kernel,
        cudaFuncAttributeMaxDynamicSharedMemorySize, smem_h);

    dim3 blk(256);

    dim3 gcx((M1 * D_) / 1024, 1, 3);
    convert_x_kernel<<<gcx, blk>>>(xa);

    dim3 gcw(D_ / 32, D_ / 32, 3);
    convert_w_kernel<<<gcw, blk>>>(wa);

    dim3 gproj(D_ / BN, M1 / BM, 3);
    proj_kernel<<<gproj, blk, smem_h>>>(pa);

    dim3 gtv(S_ / 64, D_ / 64, B_);
    transpose_v_kernel<<<gtv, blk>>>();

    dim3 gsc(S_ / BN, S_ / BM, B_);
    scores_kernel<<<gsc, blk, smem_h>>>();

    softmax_mask_kernel<<<M1, blk>>>(mask);

    dim3 gout(D_ / BN, S_ / BM, B_);
    out_kernel<<<gout, blk, smem_h>>>((float*)d_out);
}

// round 16
// speedup vs baseline: 1.1135x; 1.1135x over previous
#include <cuda_runtime.h>
#include <cuda_fp16.h>
#include <cstdint>

#define B_  8
#define S_  2048
#define D_  768
#define M1  (B_ * S_)

// ---------------- fp16 GEMM config ----------------
#define BM 128
#define BN 128
#define HBK 64                 // halves per k-tile (doubled: half the syncs)
#define HSTRIDE 72             // halves per row in smem (pad 64->72)
#define HST 3
#define H_A_BYTES (BM * HSTRIDE * 2)   // 18432
#define H_STAGE_BYTES (2 * H_A_BYTES)  // 36864
#define SMEM_H (H_STAGE_BYTES * HST)   // 110592

// ---------------- scratch ----------------
__device__ __half g_Xh [3][(size_t)M1 * D_];       // fp16 inputs q,k,v
__device__ __half g_Wth[3][(size_t)D_ * D_];       // fp16 W transposed [n][k]
__device__ __half g_Qh [(size_t)M1 * D_];
__device__ __half g_Kh [(size_t)M1 * D_];
__device__ __half g_Vth[(size_t)B_ * D_ * S_];     // V transposed [b][d][s]
__device__ float  g_S  [(size_t)B_ * S_ * S_];     // raw scores fp32
__device__ __half g_P  [(size_t)B_ * S_ * S_];     // probs fp16

// ---------------- JAX threefry2x32 (bit-exact, verified R1) ----------------
__device__ __forceinline__ uint32_t rotl32(uint32_t x, uint32_t d) {
    return (x << d) | (x >> (32u - d));
}
__device__ __forceinline__ float tf_uniform(uint32_t idx) {
    const uint32_t K0 = 0u, K1 = 42u, K2 = 0x1BD11BDAu ^ 42u;
    uint32_t x0 = 0u + K0, x1 = idx + K1;
#define TF_R4(a,b,c,d) \
    x0 += x1; x1 = rotl32(x1,(a)); x1 ^= x0; \
    x0 += x1; x1 = rotl32(x1,(b)); x1 ^= x0; \
    x0 += x1; x1 = rotl32(x1,(c)); x1 ^= x0; \
    x0 += x1; x1 = rotl32(x1,(d)); x1 ^= x0;
    TF_R4(13,15,26, 6)  x0 += K1; x1 += K2 + 1u;
    TF_R4(17,29,16,24)  x0 += K2; x1 += K0 + 2u;
    TF_R4(13,15,26, 6)  x0 += K0; x1 += K1 + 3u;
    TF_R4(17,29,16,24)  x0 += K1; x1 += K2 + 4u;
    TF_R4(13,15,26, 6)  x0 += K2; x1 += K0 + 5u;
#undef TF_R4
    uint32_t bits = x0 ^ x1;
    return __uint_as_float((bits >> 9) | 0x3f800000u) - 1.0f;
}

// ---------------- helpers ----------------
__device__ __forceinline__ void mma_f16(float (&c)[4], const uint32_t (&a)[4],
                                        const uint32_t (&b)[2]) {
    asm volatile(
        "mma.sync.aligned.m16n8k16.row.col.f32.f16.f16.f32 "
        "{%0,%1,%2,%3}, {%4,%5,%6,%7}, {%8,%9}, {%0,%1,%2,%3};"
        : "+f"(c[0]), "+f"(c[1]), "+f"(c[2]), "+f"(c[3])
        : "r"(a[0]), "r"(a[1]), "r"(a[2]), "r"(a[3]), "r"(b[0]), "r"(b[1]));
}
__device__ __forceinline__ void ldsm_x4(uint32_t& r0, uint32_t& r1,
                                        uint32_t& r2, uint32_t& r3,
                                        uint32_t addr) {
    asm volatile(
        "ldmatrix.sync.aligned.m8n8.x4.shared.b16 {%0,%1,%2,%3}, [%4];"
        : "=r"(r0), "=r"(r1), "=r"(r2), "=r"(r3) : "r"(addr));
}
__device__ __forceinline__ void cpa16(uint32_t sa, const void* g) {
    asm volatile("cp.async.cg.shared.global [%0], [%1], 16;" :: "r"(sa), "l"(g));
}
__device__ __forceinline__ void cpa_commit() {
    asm volatile("cp.async.commit_group;");
}
template <int N>
__device__ __forceinline__ void cpa_wait() {
    asm volatile("cp.async.wait_group %0;" :: "n"(N));
}

// ============ fp16 pipelined GEMM: C = A @ B^T, A [M][K], B [N][K] halves ===
// 3-stage, HBK=64 (4 k16-steps per stage). LDSM fragment loads.
__device__ __forceinline__ void gemm_h(const __half* __restrict__ A,
                                       const __half* __restrict__ Bm,
                                       int K, int row0, int col0,
                                       float (&acc)[4][4][4]) {
    extern __shared__ float smf[];
    const uint32_t sbase = (uint32_t)__cvta_generic_to_shared(smf);
    const int tid  = threadIdx.x;
    const int lane = tid & 31, warp = tid >> 5;
    const int wm = (warp & 1) * 64;
    const int wn = (warp >> 1) * 32;

#pragma unroll
    for (int mi = 0; mi < 4; ++mi)
#pragma unroll
        for (int ni = 0; ni < 4; ++ni)
#pragma unroll
            for (int q = 0; q < 4; ++q) acc[mi][ni][q] = 0.0f;

    // ldmatrix per-lane offsets (halves, relative to stage start)
    const int lane15 = lane & 15;
    const int colsel = (lane >> 4) << 3;       // 0 or 8 (k side)
    int offA[4], offB[2];
#pragma unroll
    for (int mi = 0; mi < 4; ++mi)
        offA[mi] = (wm + mi * 16 + lane15) * HSTRIDE + colsel;
#pragma unroll
    for (int p = 0; p < 2; ++p)
        offB[p] = BM * HSTRIDE + (wn + p * 16 + lane15) * HSTRIDE + colsel;

    auto load_stage = [&](int s, int it) {
        const int k0 = it * HBK;
        const uint32_t st = sbase + (uint32_t)s * H_STAGE_BYTES;
#pragma unroll
        for (int p = 0; p < 4; ++p) {           // A: 128 rows x 8 chunks(8 halves)
            const int c  = tid + (p << 8);
            const int r  = c >> 3;
            const int ch = c & 7;
            cpa16(st + (uint32_t)(r * HSTRIDE + ch * 8) * 2u,
                  A + (size_t)(row0 + r) * K + k0 + ch * 8);
        }
#pragma unroll
        for (int p = 0; p < 4; ++p) {           // B: 128 rows x 8 chunks
            const int c  = tid + (p << 8);
            const int r  = c >> 3;
            const int ch = c & 7;
            cpa16(st + H_A_BYTES + (uint32_t)(r * HSTRIDE + ch * 8) * 2u,
                  Bm + (size_t)(col0 + r) * K + k0 + ch * 8);
        }
    };

    const int nk = K / HBK;
    load_stage(0, 0); cpa_commit();
    load_stage(1, 1); cpa_commit();

    int scomp = 0, sload = 2;
    for (int i = 0; i < nk; ++i) {
        cpa_wait<1>();
        __syncthreads();
        const int ld = i + 2;
        if (ld < nk) {
            load_stage(sload, ld);
            if (++sload == HST) sload = 0;
        }
        cpa_commit();

        const uint32_t su = sbase + (uint32_t)scomp * H_STAGE_BYTES;
        if (++scomp == HST) scomp = 0;
#pragma unroll
        for (int ks = 0; ks < HBK / 16; ++ks) {
            const int k = ks << 4;
            uint32_t a[4][4];
#pragma unroll
            for (int mi = 0; mi < 4; ++mi)
                ldsm_x4(a[mi][0], a[mi][1], a[mi][2], a[mi][3],
                        su + (uint32_t)(offA[mi] + k) * 2u);
            uint32_t b[4][2];
#pragma unroll
            for (int p = 0; p < 2; ++p)
                ldsm_x4(b[2 * p][0], b[2 * p + 1][0],
                        b[2 * p][1], b[2 * p + 1][1],
                        su + (uint32_t)(offB[p] + k) * 2u);
#pragma unroll
            for (int mi = 0; mi < 4; ++mi)
#pragma unroll
                for (int ni = 0; ni < 4; ++ni)
                    mma_f16(acc[mi][ni], a[mi], b[ni]);
        }
    }
    cpa_wait<0>();
}

// ---------------- kernel 0a: convert q/k/v fp32 -> fp16 ----------------
struct XArgs { const float* X[3]; };

__global__ __launch_bounds__(256)
void convert_x_kernel(XArgs xa) {
    const int z = blockIdx.z;
    const float* X = xa.X[z];
    __half* O = g_Xh[z];
    const size_t i = ((size_t)blockIdx.x * 256 + threadIdx.x) * 4;
    float4 v = *reinterpret_cast<const float4*>(X + i);
    __half2 h0 = __floats2half2_rn(v.x, v.y);
    __half2 h1 = __floats2half2_rn(v.z, v.w);
    *reinterpret_cast<__half2*>(O + i)     = h0;
    *reinterpret_cast<__half2*>(O + i + 2) = h1;
}

// ---------------- kernel 0b: W [K][N] -> Wt fp16 [N][K] ----------------
struct WArgs { const float* W[3]; };

__global__ __launch_bounds__(256)
void convert_w_kernel(WArgs wa) {
    __shared__ float tile[32][33];
    const int z = blockIdx.z;
    const float* W = wa.W[z];
    __half* Wt = g_Wth[z];
    const int bx = blockIdx.x * 32, by = blockIdx.y * 32;
    const int tx = threadIdx.x & 31, ty = (threadIdx.x >> 5) * 4;
#pragma unroll
    for (int i = 0; i < 4; ++i)
        tile[ty + i][tx] = W[(size_t)(by + ty + i) * D_ + bx + tx];
    __syncthreads();
#pragma unroll
    for (int i = 0; i < 4; ++i)
        Wt[(size_t)(bx + ty + i) * D_ + by + tx] = __float2half_rn(tile[tx][ty + i]);
}

// ---------------- kernel 1: fused Q/K/V projections (fp16 GEMM) ------------
// z==2 (V): epilogue stages the tile via smem and writes g_Vth transposed.
struct ProjArgs { const float* b[3]; };

#define TSTR 136   // transpose tile stride (halves)

__global__ __launch_bounds__(256, 2)
void proj_kernel(ProjArgs pa) {
    const int z = blockIdx.z;
    const int row0 = blockIdx.y * BM, col0 = blockIdx.x * BN;
    float acc[4][4][4];
    gemm_h(g_Xh[z], g_Wth[z], D_, row0, col0, acc);

    const float* bias = pa.b[z];
    const int tid = threadIdx.x, lane = tid & 31, warp = tid >> 5;
    const int rwl = (warp & 1) * 64 + (lane >> 2);       // local row
    const int cwl = (warp >> 1) * 32 + (lane & 3) * 2;   // local col

    if (z < 2) {
        __half* C = (z == 0) ? g_Qh : g_Kh;
#pragma unroll
        for (int mi = 0; mi < 4; ++mi) {
#pragma unroll
            for (int ni = 0; ni < 4; ++ni) {
                const int cl = cwl + (ni << 3);
                const int c = col0 + cl;
                const float bx = __ldg(bias + c), by = __ldg(bias + c + 1);
                const int r1 = row0 + rwl + (mi << 4);
                __half2 h0 = __floats2half2_rn(acc[mi][ni][0] + bx,
                                               acc[mi][ni][1] + by);
                __half2 h1 = __floats2half2_rn(acc[mi][ni][2] + bx,
                                               acc[mi][ni][3] + by);
                *reinterpret_cast<__half2*>(C + (size_t)r1 * D_ + c)       = h0;
                *reinterpret_cast<__half2*>(C + (size_t)(r1 + 8) * D_ + c) = h1;
            }
        }
    } else {
        // stage transposed tile T[c][r] in smem, then write g_Vth coalesced
        extern __shared__ float smf[];
        __half* T = reinterpret_cast<__half*>(smf);
        __syncthreads();   // all warps done reading stage smem
#pragma unroll
        for (int mi = 0; mi < 4; ++mi) {
#pragma unroll
            for (int ni = 0; ni < 4; ++ni) {
                const int cl = cwl + (ni << 3);
                const int c = col0 + cl;
                const float bx = __ldg(bias + c), by = __ldg(bias + c + 1);
                const int r1 = rwl + (mi << 4);
                T[(cl + 0) * TSTR + r1]     = __float2half_rn(acc[mi][ni][0] + bx);
                T[(cl + 1) * TSTR + r1]     = __float2half_rn(acc[mi][ni][1] + by);
                T[(cl + 0) * TSTR + r1 + 8] = __float2half_rn(acc[mi][ni][2] + bx);
                T[(cl + 1) * TSTR + r1 + 8] = __float2half_rn(acc[mi][ni][3] + by);
            }
        }
        __syncthreads();
        const int batch = row0 >> 11;
        const int s0 = row0 & 2047;
#pragma unroll
        for (int p = 0; p < 8; ++p) {
            const int idx = tid + (p << 8);
            const int d  = idx >> 4;            // 0..127
            const int sc = (idx & 15) << 3;     // 0..120
            uint4 v = *reinterpret_cast<const uint4*>(&T[d * TSTR + sc]);
            *reinterpret_cast<uint4*>(
                g_Vth + ((size_t)batch * D_ + col0 + d) * S_ + s0 + sc) = v;
        }
    }
}

// ------- kernel 2: scores = (Q K^T)/sqrt(D) + pre-softmax dropout (fp32 out)
__global__ __launch_bounds__(256, 2)
void scores_kernel() {
    const int bz = blockIdx.z;
    const int row0 = blockIdx.y * BM, col0 = blockIdx.x * BN;
    float acc[4][4][4];
    gemm_h(g_Qh + (size_t)bz * S_ * D_, g_Kh + (size_t)bz * S_ * D_,
           D_, row0, col0, acc);

    float* C = g_S + (size_t)bz * S_ * S_;
    const int tid = threadIdx.x, lane = tid & 31, warp = tid >> 5;
    const int rw0 = row0 + (warp & 1) * 64 + (lane >> 2);
    const int cw0 = col0 + (warp >> 1) * 32 + (lane & 3) * 2;
    const float sc = 0.03608439182435161f;  // 1/sqrt(768)
#pragma unroll
    for (int mi = 0; mi < 4; ++mi) {
#pragma unroll
        for (int rr = 0; rr < 2; ++rr) {
            const int r = rw0 + (mi << 4) + (rr << 3);
            const uint32_t ib = ((uint32_t)bz * S_ + (uint32_t)r) * (uint32_t)S_;
#pragma unroll
            for (int ni = 0; ni < 4; ++ni) {
                const int c = cw0 + (ni << 3);
                const float v0 = acc[mi][ni][rr * 2 + 0] * sc;
                const float v1 = acc[mi][ni][rr * 2 + 1] * sc;
                const float u0 = tf_uniform(ib + (uint32_t)c);
                const float u1 = tf_uniform(ib + (uint32_t)c + 1u);
                float2 o;
                o.x = (u0 < 0.8f) ? v0 * 1.25f : 0.0f;
                o.y = (u1 < 0.8f) ? v1 * 1.25f : 0.0f;
                *reinterpret_cast<float2*>(C + (size_t)r * S_ + c) = o;
            }
        }
    }
}

// ------ kernel 3: softmax over k, post-softmax mask, write fp16 probs ------
__global__ __launch_bounds__(256)
void softmax_mask_kernel(const int* __restrict__ mask) {
    const int row = blockIdx.x;
    const float* srow = g_S + (size_t)row * S_;
    __half* prow = g_P + (size_t)row * S_;
    const int* mrow = mask + (size_t)row * S_;
    const int t = threadIdx.x;
    __shared__ float red[8];

    float4 v4[2];
    v4[0] = *reinterpret_cast<const float4*>(srow + (t << 2));
    v4[1] = *reinterpret_cast<const float4*>(srow + 1024 + (t << 2));
    float* v = reinterpret_cast<float*>(v4);

    float mx = v[0];
#pragma unroll
    for (int i = 1; i < 8; ++i) mx = fmaxf(mx, v[i]);
#pragma unroll
    for (int o = 16; o > 0; o >>= 1)
        mx = fmaxf(mx, __shfl_xor_sync(0xffffffffu, mx, o));
    if ((t & 31) == 0) red[t >> 5] = mx;
    __syncthreads();
    if (t < 32) {
        float m2 = (t < 8) ? red[t] : -3.4e38f;
#pragma unroll
        for (int o = 4; o > 0; o >>= 1)
            m2 = fmaxf(m2, __shfl_xor_sync(0xffffffffu, m2, o));
        if (t == 0) red[0] = m2;
    }
    __syncthreads();
    mx = red[0];
    __syncthreads();

    float sum = 0.0f;
#pragma unroll
    for (int i = 0; i < 8; ++i) { v[i] = __expf(v[i] - mx); sum += v[i]; }
#pragma unroll
    for (int o = 16; o > 0; o >>= 1)
        sum += __shfl_xor_sync(0xffffffffu, sum, o);
    if ((t & 31) == 0) red[t >> 5] = sum;
    __syncthreads();
    if (t < 32) {
        float s2 = (t < 8) ? red[t] : 0.0f;
#pragma unroll
        for (int o = 4; o > 0; o >>= 1)
            s2 += __shfl_xor_sync(0xffffffffu, s2, o);
        if (t == 0) red[0] = s2;
    }
    __syncthreads();
    const float inv = 1.0f / red[0];

    int4 m4[2];
    m4[0] = *reinterpret_cast<const int4*>(mrow + (t << 2));
    m4[1] = *reinterpret_cast<const int4*>(mrow + 1024 + (t << 2));
    const int* m = reinterpret_cast<const int*>(m4);
#pragma unroll
    for (int i = 0; i < 8; ++i)
        v[i] = (m[i] == 0) ? 1e-9f : v[i] * inv;
#pragma unroll
    for (int p = 0; p < 2; ++p) {
        __half2 h0 = __floats2half2_rn(v[p * 4 + 0], v[p * 4 + 1]);
        __half2 h1 = __floats2half2_rn(v[p * 4 + 2], v[p * 4 + 3]);
        const int base = p * 1024 + (t << 2);
        *reinterpret_cast<__half2*>(prow + base)     = h0;
        *reinterpret_cast<__half2*>(prow + base + 2) = h1;
    }
}

// -------- kernel 4: out = att @ V  (A = probs fp16, B = Vt fp16 BTRANS) ----
__global__ __launch_bounds__(256, 2)
void out_kernel(float* __restrict__ Og) {
    const int bz = blockIdx.z;
    const int row0 = blockIdx.y * BM, col0 = blockIdx.x * BN;
    float acc[4][4][4];
    gemm_h(g_P + (size_t)bz * S_ * S_, g_Vth + (size_t)bz * D_ * S_,
           S_, row0, col0, acc);

    float* C = Og + (size_t)bz * S_ * D_;
    const int tid = threadIdx.x, lane = tid & 31, warp = tid >> 5;
    const int rw0 = row0 + (warp & 1) * 64 + (lane >> 2);
    const int cw0 = col0 + (warp >> 1) * 32 + (lane & 3) * 2;
#pragma unroll
    for (int mi = 0; mi < 4; ++mi) {
#pragma unroll
        for (int ni = 0; ni < 4; ++ni) {
            const int c = cw0 + (ni << 3);
            const int r1 = rw0 + (mi << 4);
            float2 o0 = make_float2(acc[mi][ni][0], acc[mi][ni][1]);
            float2 o1 = make_float2(acc[mi][ni][2], acc[mi][ni][3]);
            *reinterpret_cast<float2*>(C + (size_t)r1 * D_ + c)       = o0;
            *reinterpret_cast<float2*>(C + (size_t)(r1 + 8) * D_ + c) = o1;
        }
    }
}

// ---------------- launch ----------------
extern "C" void kernel_launch(void* const* d_in, const int* in_sizes, int n_in,
                              void* d_out, int out_size) {
    const int* mask = (const int*)d_in[3];

    XArgs xa;
    xa.X[0] = (const float*)d_in[0];
    xa.X[1] = (const float*)d_in[1];
    xa.X[2] = (const float*)d_in[2];

    WArgs wa;
    wa.W[0] = (const float*)d_in[4];
    wa.W[1] = (const float*)d_in[6];
    wa.W[2] = (const float*)d_in[8];

    ProjArgs pa;
    pa.b[0] = (const float*)d_in[5];
    pa.b[1] = (const float*)d_in[7];
    pa.b[2] = (const float*)d_in[9];

    cudaFuncSetAttribute(proj_kernel,
        cudaFuncAttributeMaxDynamicSharedMemorySize, SMEM_H);
    cudaFuncSetAttribute(scores_kernel,
        cudaFuncAttributeMaxDynamicSharedMemorySize, SMEM_H);
    cudaFuncSetAttribute(out_kernel,
        cudaFuncAttributeMaxDynamicSharedMemorySize, SMEM_H);

    dim3 blk(256);

    dim3 gcx((M1 * D_) / 1024, 1, 3);
    convert_x_kernel<<<gcx, blk>>>(xa);

    dim3 gcw(D_ / 32, D_ / 32, 3);
    convert_w_kernel<<<gcw, blk>>>(wa);

    dim3 gproj(D_ / BN, M1 / BM, 3);
    proj_kernel<<<gproj, blk, SMEM_H>>>(pa);

    dim3 gsc(S_ / BN, S_ / BM, B_);
    scores_kernel<<<gsc, blk, SMEM_H>>>();

    softmax_mask_kernel<<<M1, blk>>>(mask);

    dim3 gout(D_ / BN, S_ / BM, B_);
    out_kernel<<<gout, blk, SMEM_H>>>((float*)d_out);
}